// round 9
// baseline (speedup 1.0000x reference)
#include <cuda_runtime.h>
#include <math.h>

// mParametricLIF: x [N=128, T=64, D=4096] f32 -> spikes [N,T,D] f32.
//   m = lam*m + k*(x - v);  v += m;  s = (v >= th);  v = s ? 0 : v;  out = s
// k = sigmoid(tau_param[0]), lam = lamb[0], th = th[0].
//
// R9 vs R8 (46.4us, regs=79, occ 32%: register-resident prefetch killed occ)
// and R2-best (40.5us, regs=48, sawtooth loads):
//  - prefetch FIFO moved to SMEM via cp.async.cg (LDGSTS): deep in-flight
//    queue (8 stages x 2KB/block, 112KB/SM) at ~32 regs -> grid-limited occ.
//  - per-thread FIFO: each thread cp.asyncs exactly the float4 it consumes;
//    wait_group is per-thread, NO block barriers anywhere.
//  - stage-major smem layout: conflict-free LDS.128.
//  - .cg bypasses L1; stores stay __stcs (write-once, evict-first).
//  - float4 lanes, block=128, grid=1024 (98.8% wave balance).

#define S  8      // pipeline stages (prefetch distance in timesteps)
#define BT 128    // threads per block

#define CP_ASYNC16(saddr, gptr)                                             \
    asm volatile("cp.async.cg.shared.global [%0], [%1], 16;\n"              \
                 :: "r"(saddr), "l"(gptr) : "memory")
#define CP_COMMIT()  asm volatile("cp.async.commit_group;\n" ::: "memory")
#define CP_WAIT(n)   asm volatile("cp.async.wait_group %0;\n" :: "n"(n) : "memory")

__device__ __forceinline__ void lif_step(float4 xv, float4& v, float4& m,
                                         float k, float lam, float th,
                                         float4& s)
{
    m.x = lam * m.x + k * (xv.x - v.x); v.x += m.x;
    m.y = lam * m.y + k * (xv.y - v.y); v.y += m.y;
    m.z = lam * m.z + k * (xv.z - v.z); v.z += m.z;
    m.w = lam * m.w + k * (xv.w - v.w); v.w += m.w;

    s.x = (v.x >= th) ? 1.0f : 0.0f;
    s.y = (v.y >= th) ? 1.0f : 0.0f;
    s.z = (v.z >= th) ? 1.0f : 0.0f;
    s.w = (v.w >= th) ? 1.0f : 0.0f;

    v.x = (s.x != 0.0f) ? 0.0f : v.x;
    v.y = (s.y != 0.0f) ? 0.0f : v.y;
    v.z = (s.z != 0.0f) ? 0.0f : v.z;
    v.w = (s.w != 0.0f) ? 0.0f : v.w;
}

__global__ __launch_bounds__(BT) void mplif_kernel(
    const float4* __restrict__ x4,
    const float* __restrict__ tau_param,
    const float* __restrict__ lamb,
    const float* __restrict__ thr,
    float4* __restrict__ out4,
    int T, int DC /* D/4 */)
{
    __shared__ float4 stage[S][BT];   // stage-major: conflict-free LDS.128

    int tid = blockIdx.x * BT + threadIdx.x;     // lanes = 1024*128 exactly
    int n = tid / DC;
    int c = tid - n * DC;
    long base = (long)n * T * DC + c;

    const float k   = 1.0f / (1.0f + expf(-tau_param[0]));
    const float lam = lamb[0];
    const float th  = thr[0];

    const float4* __restrict__ px = x4 + base;    // prefetch cursor
    float4*       __restrict__ po = out4 + base;  // store cursor

    unsigned int s_base =
        (unsigned int)__cvta_generic_to_shared(&stage[0][threadIdx.x]);
    const unsigned int s_stride = BT * sizeof(float4);  // 2048 B per stage

    float4 v = make_float4(0.f, 0.f, 0.f, 0.f);
    float4 m = make_float4(0.f, 0.f, 0.f, 0.f);

    // Prologue: fill S stages.
    #pragma unroll
    for (int j = 0; j < S; j++) {
        CP_ASYNC16(s_base + j * s_stride, px);
        CP_COMMIT();
        px += DC;
    }

    // Steady state: wait oldest, consume slot j, refill slot j with t+S.
    for (int t0 = 0; t0 < T - S; t0 += S) {
        #pragma unroll
        for (int j = 0; j < S; j++) {
            CP_WAIT(S - 1);                       // stage j (group t0+j) ready
            float4 xv = stage[j][threadIdx.x];
            CP_ASYNC16(s_base + j * s_stride, px);  // refill AFTER consume
            CP_COMMIT();
            px += DC;
            float4 s;
            lif_step(xv, v, m, k, lam, th, s);
            __stcs(po, s);
            po += DC;
        }
    }

    // Epilogue: last S timesteps, all loads already issued.
    CP_WAIT(0);
    #pragma unroll
    for (int j = 0; j < S; j++) {
        float4 s;
        lif_step(stage[j][threadIdx.x], v, m, k, lam, th, s);
        __stcs(po, s);
        po += DC;
    }
}

extern "C" void kernel_launch(void* const* d_in, const int* in_sizes, int n_in,
                              void* d_out, int out_size)
{
    const float* x         = (const float*)d_in[0];
    const float* tau_param = (const float*)d_in[1];
    const float* lamb      = (const float*)d_in[2];
    const float* th        = (const float*)d_in[3];
    float* out             = (float*)d_out;

    const int N = 128, T = 64, D = 4096;
    const int DC = D / 4;
    const int lanes = N * DC;

    dim3 block(BT);
    dim3 grid(lanes / BT);   // 1024 blocks, exact
    mplif_kernel<<<grid, block>>>((const float4*)x, tau_param, lamb, th,
                                  (float4*)out, T, DC);
}